// round 13
// baseline (speedup 1.0000x reference)
#include <cuda_runtime.h>
#include <math.h>

// ---------------------------------------------------------------------------
// Coefficient computation, executed by ONE warp per block (lanes 0-31).
// Lane j (j = lane & 3) evolves column j of the total unitary through the
// L layers:  layer = CP @ D @ S @ P @ HH @ CNOT, with S,P,CP diagonal,
// D = kron(2x2,2x2), G = HH@CNOT a constant +-0.5 real matrix.
// Epilogue folds state phases ph=(1,-i,-i,-1) into columns; the observable
// collapses to 9 real trig coefficients written to k_out (smem).
// Order: [const, C0, C1, C0C1, S0, S1, S0C1, C0S1, S0S1]
// ---------------------------------------------------------------------------
__device__ __forceinline__ void compute_coeffs_warp(
        const float* __restrict__ params,
        const float* __restrict__ W,
        const float* __restrict__ bias,
        int L, float* k_out) {
    const unsigned FULL = 0xFFFFFFFFu;
    int lane = threadIdx.x & 31;
    int col = lane & 3;

    float ur[4], ui[4];
    #pragma unroll
    for (int i = 0; i < 4; i++) { ur[i] = (i == col) ? 1.f : 0.f; ui[i] = 0.f; }

    for (int l = 0; l < L; l++) {
        float p[14];
        #pragma unroll
        for (int j = 0; j < 14; j++) {
            float v = params[l * 14 + j];
            float lim = (j < 12) ? 5.f : 1.f;
            p[j] = fminf(fmaxf(v, -lim), lim);
        }

        // t = G @ u  (G[i][j] = HH[i][cnot(j)], cnot: 2<->3, entries +-0.5)
        float tr[4], ti[4];
        #pragma unroll
        for (int i = 0; i < 4; i++) {
            float ar = 0.f, ai = 0.f;
            #pragma unroll
            for (int j = 0; j < 4; j++) {
                int jp = (j < 2) ? j : (5 - j);
                float s = 0.5f;
                if ((i >> 1) & (jp >> 1)) s = -s;
                if ((i & 1) & (jp & 1))   s = -s;
                ar = fmaf(s, ur[j], ar);
                ai = fmaf(s, ui[j], ai);
            }
            tr[i] = ar; ti[i] = ai;
        }

        // diag(S*P)
        float ta = p[4] + p[6], tb = p[5] + p[7];
        #pragma unroll
        for (int i = 0; i < 4; i++) {
            float th = p[2] * (float)((i >> 1) & 1) + p[3] * (float)(i & 1)
                     + (((i >> 1) & 1) ? 0.5f : -0.5f) * ta
                     + ((i & 1) ? 0.5f : -0.5f) * tb;
            float sn, cs; __sincosf(th, &sn, &cs);
            float r  = tr[i] * cs - ti[i] * sn;
            float im = tr[i] * sn + ti[i] * cs;
            tr[i] = r; ti[i] = im;
        }

        // D = kron(ry(p10)@rz(p8), ry(p11)@rz(p9))
        float m0r[2][2], m0i[2][2], m1r[2][2], m1i[2][2];
        {
            float c, s, e0s, e0c, e1s, e1c;
            __sincosf(0.5f * p[10], &s, &c);
            __sincosf(-0.5f * p[8], &e0s, &e0c);
            __sincosf( 0.5f * p[8], &e1s, &e1c);
            m0r[0][0] =  c * e0c; m0i[0][0] =  c * e0s;
            m0r[0][1] = -s * e1c; m0i[0][1] = -s * e1s;
            m0r[1][0] =  s * e0c; m0i[1][0] =  s * e0s;
            m0r[1][1] =  c * e1c; m0i[1][1] =  c * e1s;
        }
        {
            float c, s, e0s, e0c, e1s, e1c;
            __sincosf(0.5f * p[11], &s, &c);
            __sincosf(-0.5f * p[9], &e0s, &e0c);
            __sincosf( 0.5f * p[9], &e1s, &e1c);
            m1r[0][0] =  c * e0c; m1i[0][0] =  c * e0s;
            m1r[0][1] = -s * e1c; m1i[0][1] = -s * e1s;
            m1r[1][0] =  s * e0c; m1i[1][0] =  s * e0s;
            m1r[1][1] =  c * e1c; m1i[1][1] =  c * e1s;
        }
        float nr[4], ni[4];
        #pragma unroll
        for (int i = 0; i < 4; i++) {
            float ar = 0.f, ai = 0.f;
            #pragma unroll
            for (int j = 0; j < 4; j++) {
                float dr = m0r[i >> 1][j >> 1] * m1r[i & 1][j & 1]
                         - m0i[i >> 1][j >> 1] * m1i[i & 1][j & 1];
                float di = m0r[i >> 1][j >> 1] * m1i[i & 1][j & 1]
                         + m0i[i >> 1][j >> 1] * m1r[i & 1][j & 1];
                ar += dr * tr[j] - di * ti[j];
                ai += dr * ti[j] + di * tr[j];
            }
            nr[i] = ar; ni[i] = ai;
        }

        // CP: element 3 *= e^{i(p12+p13)}
        {
            float sn, cs; __sincosf(p[12] + p[13], &sn, &cs);
            float r  = nr[3] * cs - ni[3] * sn;
            float im = nr[3] * sn + ni[3] * cs;
            nr[3] = r; ni[3] = im;
        }

        #pragma unroll
        for (int i = 0; i < 4; i++) { ur[i] = nr[i]; ui[i] = ni[i]; }
    }

    // fold state phase ph=(1,-i,-i,-1) into this column
    if (col == 1 || col == 2) {
        #pragma unroll
        for (int i = 0; i < 4; i++) { float r = ur[i]; ur[i] = ui[i]; ui[i] = -r; }
    } else if (col == 3) {
        #pragma unroll
        for (int i = 0; i < 4; i++) { ur[i] = -ur[i]; ui[i] = -ui[i]; }
    }

    // gather V; lane 0 does the tiny epilogue
    float Vr[4][4], Vi[4][4];
    #pragma unroll
    for (int j = 0; j < 4; j++)
        #pragma unroll
        for (int i = 0; i < 4; i++) {
            Vr[i][j] = __shfl_sync(FULL, ur[i], j);
            Vi[i][j] = __shfl_sync(FULL, ui[i], j);
        }

    if (lane == 0) {
        float A[4][4];
        #pragma unroll
        for (int j = 0; j < 4; j++)
            #pragma unroll
            for (int kk = 0; kk < 4; kk++) {
                float acc = 0.f;
                #pragma unroll
                for (int i = 0; i < 4; i++) {
                    float z = (i < 2) ? 1.f : -1.f;
                    acc += z * (Vr[i][j] * Vr[i][kk] + Vi[i][j] * Vi[i][kk]);
                }
                A[j][kk] = acc;
            }

        float cC   = A[0][0] + A[1][1] + A[2][2] + A[3][3];
        float cC0  = A[0][0] + A[1][1] - A[2][2] - A[3][3];
        float cC1  = A[0][0] - A[1][1] + A[2][2] - A[3][3];
        float cCC  = A[0][0] - A[1][1] - A[2][2] + A[3][3];
        float cS1   = 2.f * (A[0][1] + A[2][3]);
        float cC0S1 = 2.f * (A[0][1] - A[2][3]);
        float cS0   = 2.f * (A[0][2] + A[1][3]);
        float cS0C1 = 2.f * (A[0][2] - A[1][3]);
        float cS0S1 = 2.f * (A[0][3] + A[1][2]);

        float w = 0.25f * W[0];
        k_out[0] = w * cC + bias[0];
        k_out[1] = w * cC0;
        k_out[2] = w * cC1;
        k_out[3] = w * cCC;
        k_out[4] = w * cS0;
        k_out[5] = w * cS1;
        k_out[6] = w * cS0C1;
        k_out[7] = w * cC0S1;
        k_out[8] = w * cS0S1;
    }
}

// ---------------------------------------------------------------------------
// 256-bit x load (sm_100a legal form of L2::evict_last); addresses are
// 32B-aligned (32*t). Halves LDG count vs 2x float4.
// ---------------------------------------------------------------------------
__device__ __forceinline__ void ldg_keep256(const float4* p, float4& a, float4& b) {
    unsigned long long r0, r1, r2, r3;
    asm("ld.global.nc.L2::evict_last.v4.b64 {%0,%1,%2,%3}, [%4];"
        : "=l"(r0), "=l"(r1), "=l"(r2), "=l"(r3) : "l"(p));
    a.x = __uint_as_float((unsigned)r0);  a.y = __uint_as_float((unsigned)(r0 >> 32));
    a.z = __uint_as_float((unsigned)r1);  a.w = __uint_as_float((unsigned)(r1 >> 32));
    b.x = __uint_as_float((unsigned)r2);  b.y = __uint_as_float((unsigned)(r2 >> 32));
    b.z = __uint_as_float((unsigned)r3);  b.w = __uint_as_float((unsigned)(r3 >> 32));
}

__device__ __forceinline__ float eval_sample(float x0, float x1, const float k[9]) {
    float s0, c0, s1, c1;
    __sincosf(x0, &s0, &c0);
    __sincosf(x1, &s1, &c1);
    // v = A + c1*Bc + s1*Bs with A,Bc,Bs linear in (1, c0, s0)
    float A  = fmaf(k[1], c0, fmaf(k[4], s0, k[0]));
    float Bc = fmaf(k[3], c0, fmaf(k[6], s0, k[2]));
    float Bs = fmaf(k[7], c0, fmaf(k[8], s0, k[5]));
    return fmaf(s1, Bs, fmaf(c1, Bc, A));
}

// ---------------------------------------------------------------------------
// Single fused kernel: every thread issues its 256-bit x load FIRST
// (covering ~600cy of DRAM latency), then warp 0 computes the 9 trig
// coefficients into smem while the loads are in flight; __syncthreads;
// evaluate; streaming store. __launch_bounds__(256,8) pins 32 regs so the
// coefficient path's extra state spills to local (warp 0 only, hidden).
// ---------------------------------------------------------------------------
__global__ void __launch_bounds__(256, 8)
fraud_fused(const float4* __restrict__ x, float4* __restrict__ out, int nq,
            const float* __restrict__ params, const float* __restrict__ W,
            const float* __restrict__ bias, int L) {
    __shared__ float sk[9];
    int t = blockIdx.x * blockDim.x + threadIdx.x;
    bool act = t < nq;

    float4 a, b;
    if (act) ldg_keep256(&x[2 * t], a, b);

    if (threadIdx.x < 32)
        compute_coeffs_warp(params, W, bias, L, sk);
    __syncthreads();

    float k[9];
    #pragma unroll
    for (int i = 0; i < 9; i++) k[i] = sk[i];

    if (act) {
        float4 r;
        r.x = eval_sample(a.x, a.y, k);
        r.y = eval_sample(a.z, a.w, k);
        r.z = eval_sample(b.x, b.y, k);
        r.w = eval_sample(b.z, b.w, k);
        __stcs(&out[t], r);   // evict-first: out is never re-read
    }
}

// Scalar fallback (B not divisible by 4; not hit for this problem's shapes).
__global__ void __launch_bounds__(256, 8)
fraud_fused_scalar(const float2* __restrict__ x, float* __restrict__ out, int B,
                   const float* __restrict__ params, const float* __restrict__ W,
                   const float* __restrict__ bias, int L) {
    __shared__ float sk[9];
    int t = blockIdx.x * blockDim.x + threadIdx.x;
    bool act = t < B;
    float2 a;
    if (act) a = x[t];
    if (threadIdx.x < 32)
        compute_coeffs_warp(params, W, bias, L, sk);
    __syncthreads();
    float k[9];
    #pragma unroll
    for (int i = 0; i < 9; i++) k[i] = sk[i];
    if (act) out[t] = eval_sample(a.x, a.y, k);
}

extern "C" void kernel_launch(void* const* d_in, const int* in_sizes, int n_in,
                              void* d_out, int out_size) {
    const float* x      = (const float*)d_in[0];
    const float* params = (const float*)d_in[1];
    const float* W      = (const float*)d_in[2];
    const float* bias   = (const float*)d_in[3];
    float* out = (float*)d_out;

    int L = in_sizes[1] / 14;
    int B = out_size;  // n_classes = 1 -> out_size == batch

    if ((B & 3) == 0) {
        int nq = B >> 2;
        int blocks = (nq + 255) / 256;
        fraud_fused<<<blocks, 256>>>((const float4*)x, (float4*)out, nq,
                                     params, W, bias, L);
    } else {
        int blocks = (B + 255) / 256;
        fraud_fused_scalar<<<blocks, 256>>>((const float2*)x, out, B,
                                            params, W, bias, L);
    }
}

// round 14
// speedup vs baseline: 2.0156x; 2.0156x over previous
#include <cuda_runtime.h>
#include <math.h>

// 9 trig coefficients, computed on-device from params/W/b by setup_kernel.
// Order: [const, C0, C1, C0C1, S0, S1, S0C1, C0S1, S0S1]
__device__ float g_k[9];

// ---------------------------------------------------------------------------
// Setup: one warp. Lane j (j = lane & 3) evolves column j of the total
// unitary through the L layers:  layer = CP @ D @ S @ P @ HH @ CNOT,
// with S,P,CP diagonal, D = kron(2x2,2x2), G = HH@CNOT constant +-0.5 real.
// Epilogue folds state phases ph=(1,-i,-i,-1) into the columns; observable
// collapses to 9 real trig coefficients. Templated on compile-time layer
// count so all param loads + sincos are hoisted ahead of the FMA chain.
// ---------------------------------------------------------------------------
template <int LFIX>
__device__ __forceinline__ void setup_body(const float* __restrict__ params,
                                           const float* __restrict__ W,
                                           const float* __restrict__ bias,
                                           int Lrt) {
    const unsigned FULL = 0xFFFFFFFFu;
    int lane = threadIdx.x;
    int col = lane & 3;
    const int L = (LFIX > 0) ? LFIX : Lrt;

    float ur[4], ui[4];
    #pragma unroll
    for (int i = 0; i < 4; i++) { ur[i] = (i == col) ? 1.f : 0.f; ui[i] = 0.f; }

    #pragma unroll
    for (int l = 0; l < L; l++) {
        float p[14];
        #pragma unroll
        for (int j = 0; j < 14; j++) {
            float v = params[l * 14 + j];
            float lim = (j < 12) ? 5.f : 1.f;
            p[j] = fminf(fmaxf(v, -lim), lim);
        }

        // t = G @ u  (G[i][j] = HH[i][cnot(j)], cnot: 2<->3, entries +-0.5)
        float tr[4], ti[4];
        #pragma unroll
        for (int i = 0; i < 4; i++) {
            float ar = 0.f, ai = 0.f;
            #pragma unroll
            for (int j = 0; j < 4; j++) {
                int jp = (j < 2) ? j : (5 - j);
                float s = 0.5f;
                if ((i >> 1) & (jp >> 1)) s = -s;
                if ((i & 1) & (jp & 1))   s = -s;
                ar = fmaf(s, ur[j], ar);
                ai = fmaf(s, ui[j], ai);
            }
            tr[i] = ar; ti[i] = ai;
        }

        // diag(S*P)
        float ta = p[4] + p[6], tb = p[5] + p[7];
        #pragma unroll
        for (int i = 0; i < 4; i++) {
            float th = p[2] * (float)((i >> 1) & 1) + p[3] * (float)(i & 1)
                     + (((i >> 1) & 1) ? 0.5f : -0.5f) * ta
                     + ((i & 1) ? 0.5f : -0.5f) * tb;
            float sn, cs; __sincosf(th, &sn, &cs);
            float r  = tr[i] * cs - ti[i] * sn;
            float im = tr[i] * sn + ti[i] * cs;
            tr[i] = r; ti[i] = im;
        }

        // D = kron(ry(p10)@rz(p8), ry(p11)@rz(p9))
        float m0r[2][2], m0i[2][2], m1r[2][2], m1i[2][2];
        {
            float c, s, e0s, e0c, e1s, e1c;
            __sincosf(0.5f * p[10], &s, &c);
            __sincosf(-0.5f * p[8], &e0s, &e0c);
            __sincosf( 0.5f * p[8], &e1s, &e1c);
            m0r[0][0] =  c * e0c; m0i[0][0] =  c * e0s;
            m0r[0][1] = -s * e1c; m0i[0][1] = -s * e1s;
            m0r[1][0] =  s * e0c; m0i[1][0] =  s * e0s;
            m0r[1][1] =  c * e1c; m0i[1][1] =  c * e1s;
        }
        {
            float c, s, e0s, e0c, e1s, e1c;
            __sincosf(0.5f * p[11], &s, &c);
            __sincosf(-0.5f * p[9], &e0s, &e0c);
            __sincosf( 0.5f * p[9], &e1s, &e1c);
            m1r[0][0] =  c * e0c; m1i[0][0] =  c * e0s;
            m1r[0][1] = -s * e1c; m1i[0][1] = -s * e1s;
            m1r[1][0] =  s * e0c; m1i[1][0] =  s * e0s;
            m1r[1][1] =  c * e1c; m1i[1][1] =  c * e1s;
        }
        float nr[4], ni[4];
        #pragma unroll
        for (int i = 0; i < 4; i++) {
            float ar = 0.f, ai = 0.f;
            #pragma unroll
            for (int j = 0; j < 4; j++) {
                float dr = m0r[i >> 1][j >> 1] * m1r[i & 1][j & 1]
                         - m0i[i >> 1][j >> 1] * m1i[i & 1][j & 1];
                float di = m0r[i >> 1][j >> 1] * m1i[i & 1][j & 1]
                         + m0i[i >> 1][j >> 1] * m1r[i & 1][j & 1];
                ar += dr * tr[j] - di * ti[j];
                ai += dr * ti[j] + di * tr[j];
            }
            nr[i] = ar; ni[i] = ai;
        }

        // CP: element 3 *= e^{i(p12+p13)}
        {
            float sn, cs; __sincosf(p[12] + p[13], &sn, &cs);
            float r  = nr[3] * cs - ni[3] * sn;
            float im = nr[3] * sn + ni[3] * cs;
            nr[3] = r; ni[3] = im;
        }

        #pragma unroll
        for (int i = 0; i < 4; i++) { ur[i] = nr[i]; ui[i] = ni[i]; }
    }

    // fold state phase ph=(1,-i,-i,-1) into this column
    if (col == 1 || col == 2) {
        #pragma unroll
        for (int i = 0; i < 4; i++) { float r = ur[i]; ur[i] = ui[i]; ui[i] = -r; }
    } else if (col == 3) {
        #pragma unroll
        for (int i = 0; i < 4; i++) { ur[i] = -ur[i]; ui[i] = -ui[i]; }
    }

    // gather V into lane 0
    float Vr[4][4], Vi[4][4];
    #pragma unroll
    for (int j = 0; j < 4; j++)
        #pragma unroll
        for (int i = 0; i < 4; i++) {
            Vr[i][j] = __shfl_sync(FULL, ur[i], j);
            Vi[i][j] = __shfl_sync(FULL, ui[i], j);
        }

    if (lane == 0) {
        float A[4][4];
        #pragma unroll
        for (int j = 0; j < 4; j++)
            #pragma unroll
            for (int kk = 0; kk < 4; kk++) {
                float acc = 0.f;
                #pragma unroll
                for (int i = 0; i < 4; i++) {
                    float z = (i < 2) ? 1.f : -1.f;
                    acc += z * (Vr[i][j] * Vr[i][kk] + Vi[i][j] * Vi[i][kk]);
                }
                A[j][kk] = acc;
            }

        float cC   = A[0][0] + A[1][1] + A[2][2] + A[3][3];
        float cC0  = A[0][0] + A[1][1] - A[2][2] - A[3][3];
        float cC1  = A[0][0] - A[1][1] + A[2][2] - A[3][3];
        float cCC  = A[0][0] - A[1][1] - A[2][2] + A[3][3];
        float cS1   = 2.f * (A[0][1] + A[2][3]);
        float cC0S1 = 2.f * (A[0][1] - A[2][3]);
        float cS0   = 2.f * (A[0][2] + A[1][3]);
        float cS0C1 = 2.f * (A[0][2] - A[1][3]);
        float cS0S1 = 2.f * (A[0][3] + A[1][2]);

        float w = 0.25f * W[0];
        g_k[0] = w * cC + bias[0];
        g_k[1] = w * cC0;
        g_k[2] = w * cC1;
        g_k[3] = w * cCC;
        g_k[4] = w * cS0;
        g_k[5] = w * cS1;
        g_k[6] = w * cS0C1;
        g_k[7] = w * cC0S1;
        g_k[8] = w * cS0S1;
    }
}

template <int LFIX>
__global__ void setup_kernel_t(const float* __restrict__ params,
                               const float* __restrict__ W,
                               const float* __restrict__ bias, int Lrt) {
    setup_body<LFIX>(params, W, bias, Lrt);
}

// ---------------------------------------------------------------------------
// Streaming kernel. One 256-bit load per thread (8 floats, 32B-aligned),
// which is also the sm_100a-legal carrier for the L2::evict_last hint.
// out is write-once -> store with evict-first (__stcs).
// ---------------------------------------------------------------------------
__device__ __forceinline__ void ldg_keep256(const float4* p, float4& a, float4& b) {
    unsigned long long r0, r1, r2, r3;
    asm("ld.global.nc.L2::evict_last.v4.b64 {%0,%1,%2,%3}, [%4];"
        : "=l"(r0), "=l"(r1), "=l"(r2), "=l"(r3) : "l"(p));
    a.x = __uint_as_float((unsigned)r0);  a.y = __uint_as_float((unsigned)(r0 >> 32));
    a.z = __uint_as_float((unsigned)r1);  a.w = __uint_as_float((unsigned)(r1 >> 32));
    b.x = __uint_as_float((unsigned)r2);  b.y = __uint_as_float((unsigned)(r2 >> 32));
    b.z = __uint_as_float((unsigned)r3);  b.w = __uint_as_float((unsigned)(r3 >> 32));
}

__device__ __forceinline__ float eval_sample(float x0, float x1, const float k[9]) {
    float s0, c0, s1, c1;
    __sincosf(x0, &s0, &c0);
    __sincosf(x1, &s1, &c1);
    // v = A + c1*Bc + s1*Bs with A,Bc,Bs linear in (1, c0, s0)
    float A  = fmaf(k[1], c0, fmaf(k[4], s0, k[0]));
    float Bc = fmaf(k[3], c0, fmaf(k[6], s0, k[2]));
    float Bs = fmaf(k[7], c0, fmaf(k[8], s0, k[5]));
    return fmaf(s1, Bs, fmaf(c1, Bc, A));
}

__global__ void __launch_bounds__(256)
fraud_kernel4(const float4* __restrict__ x, float4* __restrict__ out, int nq) {
    int t = blockIdx.x * blockDim.x + threadIdx.x;
    bool act = t < nq;

    float4 a, b;
    if (act) {
        ldg_keep256(&x[2 * t], a, b);
    }

    // Wait for setup_kernel completion (and visibility of g_k).
#if __CUDA_ARCH__ >= 900
    cudaGridDependencySynchronize();
#endif

    float k[9];
    #pragma unroll
    for (int i = 0; i < 9; i++) k[i] = g_k[i];

    if (act) {
        float4 r;
        r.x = eval_sample(a.x, a.y, k);
        r.y = eval_sample(a.z, a.w, k);
        r.z = eval_sample(b.x, b.y, k);
        r.w = eval_sample(b.z, b.w, k);
        __stcs(&out[t], r);   // evict-first: out is never re-read
    }
}

// Scalar fallback (B not divisible by 4; not hit for this problem's shapes).
__global__ void __launch_bounds__(256)
fraud_kernel_scalar(const float2* __restrict__ x, float* __restrict__ out, int B) {
    int t = blockIdx.x * blockDim.x + threadIdx.x;
    float k[9];
    #pragma unroll
    for (int i = 0; i < 9; i++) k[i] = g_k[i];
    if (t < B) {
        float2 a = x[t];
        out[t] = eval_sample(a.x, a.y, k);
    }
}

extern "C" void kernel_launch(void* const* d_in, const int* in_sizes, int n_in,
                              void* d_out, int out_size) {
    const float* x      = (const float*)d_in[0];
    const float* params = (const float*)d_in[1];
    const float* W      = (const float*)d_in[2];
    const float* bias   = (const float*)d_in[3];
    float* out = (float*)d_out;

    int L = in_sizes[1] / 14;
    switch (L) {
        case 1:  setup_kernel_t<1><<<1, 32>>>(params, W, bias, L); break;
        case 2:  setup_kernel_t<2><<<1, 32>>>(params, W, bias, L); break;
        case 3:  setup_kernel_t<3><<<1, 32>>>(params, W, bias, L); break;
        case 4:  setup_kernel_t<4><<<1, 32>>>(params, W, bias, L); break;
        default: setup_kernel_t<0><<<1, 32>>>(params, W, bias, L); break;
    }

    int B = out_size;  // n_classes = 1 -> out_size == batch
    if ((B & 3) == 0) {
        int nq = B >> 2;
        int blocks = (nq + 255) / 256;

        // Programmatic dependent launch: overlap main-kernel ramp-up with
        // the (short) setup kernel; correctness is guaranteed by the
        // in-kernel cudaGridDependencySynchronize().
        cudaLaunchConfig_t cfg = {};
        cfg.gridDim = dim3(blocks, 1, 1);
        cfg.blockDim = dim3(256, 1, 1);
        cfg.dynamicSmemBytes = 0;
        cfg.stream = 0;
        cudaLaunchAttribute attr[1];
        attr[0].id = cudaLaunchAttributeProgrammaticStreamSerialization;
        attr[0].val.programmaticStreamSerializationAllowed = 1;
        cfg.attrs = attr;
        cfg.numAttrs = 1;
        cudaError_t e = cudaLaunchKernelEx(&cfg, fraud_kernel4,
                                           (const float4*)x, (float4*)out, nq);
        if (e != cudaSuccess) {
            (void)cudaGetLastError();
            fraud_kernel4<<<blocks, 256>>>((const float4*)x, (float4*)out, nq);
        }
    } else {
        int blocks = (B + 255) / 256;
        fraud_kernel_scalar<<<blocks, 256>>>((const float2*)x, out, B);
    }
}